// round 5
// baseline (speedup 1.0000x reference)
#include <cuda_runtime.h>
#include <cuda_bf16.h>
#include <cstdint>

#define N_NODES 100000
#define N_EDGES 1600000
#define D 128
#define EPS 1e-5f

// ---------------- scratch ----------------
__device__ float g_aggr[(size_t)N_NODES * D];
__device__ float g_h[(size_t)N_NODES * D];
__device__ float g_sum[D];
__device__ float g_sumsq[D];
__device__ int   g_idx_is64;

// ---------------- helpers ----------------
__device__ __forceinline__ uint32_t smem_u32(const void* p) {
    uint32_t a;
    asm("{ .reg .u64 t; cvta.to.shared.u64 t, %1; cvt.u32.u64 %0, t; }"
        : "=r"(a) : "l"(p));
    return a;
}
__device__ __forceinline__ void ldsm_x4(uint32_t& r0, uint32_t& r1,
                                        uint32_t& r2, uint32_t& r3, uint32_t a) {
    asm volatile("ldmatrix.sync.aligned.m8n8.x4.shared.b16 {%0,%1,%2,%3}, [%4];"
                 : "=r"(r0), "=r"(r1), "=r"(r2), "=r"(r3) : "r"(a));
}
__device__ __forceinline__ void ldsm_x4_t(uint32_t& r0, uint32_t& r1,
                                          uint32_t& r2, uint32_t& r3, uint32_t a) {
    asm volatile("ldmatrix.sync.aligned.m8n8.x4.trans.shared.b16 {%0,%1,%2,%3}, [%4];"
                 : "=r"(r0), "=r"(r1), "=r"(r2), "=r"(r3) : "r"(a));
}
__device__ __forceinline__ void mma_bf16(float* c, const uint32_t* a, const uint32_t* b) {
    asm volatile("mma.sync.aligned.m16n8k16.row.col.f32.bf16.bf16.f32 "
                 "{%0,%1,%2,%3}, {%4,%5,%6,%7}, {%8,%9}, {%0,%1,%2,%3};"
                 : "+f"(c[0]), "+f"(c[1]), "+f"(c[2]), "+f"(c[3])
                 : "r"(a[0]), "r"(a[1]), "r"(a[2]), "r"(a[3]),
                   "r"(b[0]), "r"(b[1]));
}

// ---------------- kernel 0: detect edge_index dtype ----------------
__global__ void probe_kernel(const int* __restrict__ e) {
    __shared__ int nz;
    if (threadIdx.x == 0) nz = 0;
    __syncthreads();
    int v = e[threadIdx.x * 2 + 1];
    if (v != 0) atomicAdd(&nz, 1);
    __syncthreads();
    if (threadIdx.x == 0) g_idx_is64 = (nz == 0) ? 1 : 0;
}

// ---------------- kernel 1: zero aggr + stats ----------------
__global__ void zero_kernel() {
    int idx = blockIdx.x * blockDim.x + threadIdx.x;
    const int n4 = (N_NODES * D) / 4;
    if (idx < n4) ((float4*)g_aggr)[idx] = make_float4(0.f, 0.f, 0.f, 0.f);
    if (blockIdx.x == 0 && threadIdx.x < D) {
        g_sum[threadIdx.x] = 0.f;
        g_sumsq[threadIdx.x] = 0.f;
    }
}

// ---------------- kernel 2: edge scatter-add ----------------
__device__ __forceinline__ void red_add_v4(float* addr, float4 v) {
    asm volatile("red.global.add.v4.f32 [%0], {%1, %2, %3, %4};"
                 :: "l"(addr), "f"(v.x), "f"(v.y), "f"(v.z), "f"(v.w)
                 : "memory");
}

__global__ void scatter_kernel(const void* __restrict__ edge_index,
                               const float* __restrict__ x) {
    int warp = (blockIdx.x * blockDim.x + threadIdx.x) >> 5;
    if (warp >= N_EDGES) return;
    int lane = threadIdx.x & 31;

    long long src, dst;
    if (g_idx_is64) {
        const long long* e = (const long long*)edge_index;
        src = e[warp];
        dst = e[N_EDGES + warp];
    } else {
        const int* e = (const int*)edge_index;
        src = e[warp];
        dst = e[N_EDGES + warp];
    }
    if ((unsigned long long)src >= N_NODES || (unsigned long long)dst >= N_NODES)
        return;

    float4 v = ((const float4*)(x + (size_t)src * D))[lane];
    red_add_v4(g_aggr + (size_t)dst * D + lane * 4, v);
}

// ---------------- kernel 3: mma.sync bf16x2 GEMM + bias + BN stats --------
// h = x @ W_root + aggr @ W_rel + b_rel  (virtual K=256, 4 chunks of 64)
// fp32 -> bf16 hi/lo split; 3 MMAs per product term.
// CTA tile 128x128; 8 warps as 4(M) x 2(N); warp tile 32x64.
// smem byte offsets:
#define SA_HI 0            // 128 rows * 144 B (pitch 72 bf16)
#define SA_LO 18432
#define SB_HI 36864        // 64 rows * 272 B (pitch 136 bf16)
#define SB_LO 54272
#define SM_BIAS 71680      // 128 f32
#define SM_SSUM 72192      // 128 f32
#define SM_SSQ  72704      // 128 f32
#define GEMM_SMEM 73216

__global__ void __launch_bounds__(256)
gemm_tc_kernel(const float* __restrict__ x,
               const float* __restrict__ W_root,
               const float* __restrict__ W_rel,
               const float* __restrict__ b_rel) {
    extern __shared__ char smem[];
    const uint32_t sb = smem_u32(smem);
    const int tid = threadIdx.x;
    const int wid = tid >> 5;
    const int lid = tid & 31;
    const int wm = wid & 3;        // M warp coord (32-row slab)
    const int wn = wid >> 2;       // N warp coord (64-col slab)
    const int m0 = blockIdx.x * 128;

    if (tid < D) {
        ((float*)(smem + SM_BIAS))[tid] = b_rel[tid];
        ((float*)(smem + SM_SSUM))[tid] = 0.f;
        ((float*)(smem + SM_SSQ))[tid]  = 0.f;
    }

    float acc[2][8][4];
#pragma unroll
    for (int i = 0; i < 2; i++)
#pragma unroll
        for (int j = 0; j < 8; j++)
#pragma unroll
            for (int c = 0; c < 4; c++) acc[i][j][c] = 0.f;

#pragma unroll 1
    for (int kc = 0; kc < 4; kc++) {
        const float* Asrc = (kc < 2) ? x : g_aggr;
        const float* Wsrc = (kc < 2) ? W_root : W_rel;
        const int ka = (kc & 1) * 64;

        // ---- convert A chunk: rows m0..m0+127, cols ka..ka+63, bf16 hi/lo
        {
            int r = tid >> 1;
            int c0 = (tid & 1) * 32;
            bool valid = (m0 + r) < N_NODES;
            const float* srcp = Asrc + (size_t)(m0 + r) * D + ka + c0;
            char* rowh = smem + SA_HI + r * 144 + c0 * 2;
            char* rowl = smem + SA_LO + r * 144 + c0 * 2;
#pragma unroll
            for (int j = 0; j < 32; j += 2) {
                float2 v = valid ? *(const float2*)(srcp + j) : make_float2(0.f, 0.f);
                __nv_bfloat16 h0 = __float2bfloat16(v.x);
                __nv_bfloat16 h1 = __float2bfloat16(v.y);
                __nv_bfloat162 hp = __halves2bfloat162(h0, h1);
                __nv_bfloat162 lp = __halves2bfloat162(
                    __float2bfloat16(v.x - __bfloat162float(h0)),
                    __float2bfloat16(v.y - __bfloat162float(h1)));
                *(uint32_t*)(rowh + j * 2) = *(uint32_t*)&hp;
                *(uint32_t*)(rowl + j * 2) = *(uint32_t*)&lp;
            }
        }
        // ---- convert B chunk: W rows ka..ka+63, natural k x n layout
        {
            int kl0 = tid >> 5;
            int n4 = (tid & 31) * 4;
#pragma unroll
            for (int p = 0; p < 8; p++) {
                int kl = kl0 + p * 8;
                float4 w = *(const float4*)(Wsrc + (size_t)(ka + kl) * D + n4);
                __nv_bfloat16 h0 = __float2bfloat16(w.x);
                __nv_bfloat16 h1 = __float2bfloat16(w.y);
                __nv_bfloat16 h2 = __float2bfloat16(w.z);
                __nv_bfloat16 h3 = __float2bfloat16(w.w);
                __nv_bfloat162 hp0 = __halves2bfloat162(h0, h1);
                __nv_bfloat162 hp1 = __halves2bfloat162(h2, h3);
                __nv_bfloat162 lp0 = __halves2bfloat162(
                    __float2bfloat16(w.x - __bfloat162float(h0)),
                    __float2bfloat16(w.y - __bfloat162float(h1)));
                __nv_bfloat162 lp1 = __halves2bfloat162(
                    __float2bfloat16(w.z - __bfloat162float(h2)),
                    __float2bfloat16(w.w - __bfloat162float(h3)));
                char* bh = smem + SB_HI + kl * 272 + n4 * 2;
                char* bl = smem + SB_LO + kl * 272 + n4 * 2;
                *(uint32_t*)(bh + 0) = *(uint32_t*)&hp0;
                *(uint32_t*)(bh + 4) = *(uint32_t*)&hp1;
                *(uint32_t*)(bl + 0) = *(uint32_t*)&lp0;
                *(uint32_t*)(bl + 4) = *(uint32_t*)&lp1;
            }
        }
        __syncthreads();

        // ---- compute: 4 k16 steps
#pragma unroll
        for (int s = 0; s < 4; s++) {
            uint32_t ah[2][4], al[2][4];
#pragma unroll
            for (int mt = 0; mt < 2; mt++) {
                uint32_t aaddr = sb + SA_HI
                    + (uint32_t)((wm * 32 + mt * 16 + (lid & 15)) * 144
                                 + s * 32 + (lid >> 4) * 16);
                ldsm_x4(ah[mt][0], ah[mt][1], ah[mt][2], ah[mt][3], aaddr);
                ldsm_x4(al[mt][0], al[mt][1], al[mt][2], al[mt][3],
                        aaddr + (SA_LO - SA_HI));
            }
#pragma unroll
            for (int q = 0; q < 4; q++) {
                uint32_t bh[4], bl[4];
                uint32_t baddr = sb + SB_HI
                    + (uint32_t)((s * 16 + (lid & 15)) * 272
                                 + (wn * 64 + q * 16 + (lid >> 4) * 8) * 2);
                ldsm_x4_t(bh[0], bh[1], bh[2], bh[3], baddr);
                ldsm_x4_t(bl[0], bl[1], bl[2], bl[3], baddr + (SB_LO - SB_HI));
#pragma unroll
                for (int t = 0; t < 2; t++) {
                    const uint32_t* bhp = &bh[t * 2];
                    const uint32_t* blp = &bl[t * 2];
#pragma unroll
                    for (int mt = 0; mt < 2; mt++) {
                        float* c = acc[mt][q * 2 + t];
                        mma_bf16(c, ah[mt], bhp);
                        mma_bf16(c, ah[mt], blp);
                        mma_bf16(c, al[mt], bhp);
                    }
                }
            }
        }
        __syncthreads();
    }

    // ---- epilogue: bias + store h + BN stats
    float s_sum[8][2], s_sq[8][2];
#pragma unroll
    for (int j = 0; j < 8; j++) {
        s_sum[j][0] = s_sum[j][1] = 0.f;
        s_sq[j][0] = s_sq[j][1] = 0.f;
    }
    const float* bias = (const float*)(smem + SM_BIAS);
    const int ncol0 = wn * 64 + (lid & 3) * 2;

#pragma unroll
    for (int mt = 0; mt < 2; mt++) {
#pragma unroll
        for (int h2 = 0; h2 < 2; h2++) {
            int m = m0 + wm * 32 + mt * 16 + (lid >> 2) + h2 * 8;
            if (m < N_NODES) {
                float* dst = g_h + (size_t)m * D;
#pragma unroll
                for (int jn = 0; jn < 8; jn++) {
                    int n = ncol0 + jn * 8;
                    float v0 = acc[mt][jn][h2 * 2 + 0] + bias[n];
                    float v1 = acc[mt][jn][h2 * 2 + 1] + bias[n + 1];
                    *(float2*)(dst + n) = make_float2(v0, v1);
                    s_sum[jn][0] += v0; s_sum[jn][1] += v1;
                    s_sq[jn][0] += v0 * v0; s_sq[jn][1] += v1 * v1;
                }
            }
        }
    }
    float* ssum = (float*)(smem + SM_SSUM);
    float* ssq  = (float*)(smem + SM_SSQ);
#pragma unroll
    for (int jn = 0; jn < 8; jn++) {
        int n = ncol0 + jn * 8;
        atomicAdd(&ssum[n],     s_sum[jn][0]);
        atomicAdd(&ssum[n + 1], s_sum[jn][1]);
        atomicAdd(&ssq[n],      s_sq[jn][0]);
        atomicAdd(&ssq[n + 1],  s_sq[jn][1]);
    }
    __syncthreads();
    if (tid < D) {
        atomicAdd(&g_sum[tid],   ssum[tid]);
        atomicAdd(&g_sumsq[tid], ssq[tid]);
    }
}

// ---------------- kernel 4: fused finalize + normalize + ReLU -------------
__global__ void norm_kernel(const float* __restrict__ gamma,
                            const float* __restrict__ beta,
                            float* __restrict__ out) {
    __shared__ float ssc[D], ssh[D];
    int t = threadIdx.x;
    if (t < D) {
        float inv_n = 1.0f / (float)N_NODES;
        float mean = g_sum[t] * inv_n;
        float var = g_sumsq[t] * inv_n - mean * mean;
        float sc = gamma[t] * rsqrtf(var + EPS);
        ssc[t] = sc;
        ssh[t] = beta[t] - mean * sc;
    }
    __syncthreads();
    int idx = blockIdx.x * blockDim.x + t;
    const int n4 = (N_NODES * D) / 4;
    if (idx >= n4) return;
    int c4 = (idx & (D / 4 - 1)) * 4;
    float4 h = ((const float4*)g_h)[idx];
    float4 o;
    o.x = fmaxf(h.x * ssc[c4 + 0] + ssh[c4 + 0], 0.f);
    o.y = fmaxf(h.y * ssc[c4 + 1] + ssh[c4 + 1], 0.f);
    o.z = fmaxf(h.z * ssc[c4 + 2] + ssh[c4 + 2], 0.f);
    o.w = fmaxf(h.w * ssc[c4 + 3] + ssh[c4 + 3], 0.f);
    ((float4*)out)[idx] = o;
}

// ---------------- launch ----------------
extern "C" void kernel_launch(void* const* d_in, const int* in_sizes, int n_in,
                              void* d_out, int out_size) {
    const float* x      = (const float*)d_in[0];
    const void*  eidx   = d_in[1];
    const float* W_root = (const float*)d_in[2];
    const float* W_rel  = (const float*)d_in[3];
    const float* b_rel  = (const float*)d_in[4];
    const float* gamma  = (const float*)d_in[5];
    const float* beta   = (const float*)d_in[6];
    float*       out    = (float*)d_out;

    cudaFuncSetAttribute(gemm_tc_kernel,
                         cudaFuncAttributeMaxDynamicSharedMemorySize, GEMM_SMEM);

    probe_kernel<<<1, 64>>>((const int*)eidx);

    const int n4 = (N_NODES * D) / 4;
    zero_kernel<<<(n4 + 255) / 256, 256>>>();

    scatter_kernel<<<(N_EDGES + 7) / 8, 256>>>(eidx, x);

    gemm_tc_kernel<<<(N_NODES + 127) / 128, 256, GEMM_SMEM>>>(x, W_root, W_rel, b_rel);

    norm_kernel<<<(n4 + 255) / 256, 256>>>(gamma, beta, out);
}

// round 6
// speedup vs baseline: 1.1720x; 1.1720x over previous
#include <cuda_runtime.h>
#include <cuda_bf16.h>
#include <cstdint>

#define N_NODES 100000
#define N_EDGES 1600000
#define D 128
#define EPS 1e-5f

// ---------------- scratch ----------------
__device__ float g_aggr[(size_t)N_NODES * D];
__device__ float g_h[(size_t)N_NODES * D];
__device__ float g_sum[D];
__device__ float g_sumsq[D];
__device__ int   g_idx_is64;
__device__ __nv_bfloat16 gW_hi[256 * 128];   // rows 0-127 W_root, 128-255 W_rel
__device__ __nv_bfloat16 gW_lo[256 * 128];

// ---------------- helpers ----------------
__device__ __forceinline__ uint32_t smem_u32(const void* p) {
    uint32_t a;
    asm("{ .reg .u64 t; cvta.to.shared.u64 t, %1; cvt.u32.u64 %0, t; }"
        : "=r"(a) : "l"(p));
    return a;
}
__device__ __forceinline__ void ldsm_x4_t(uint32_t& r0, uint32_t& r1,
                                          uint32_t& r2, uint32_t& r3, uint32_t a) {
    asm volatile("ldmatrix.sync.aligned.m8n8.x4.trans.shared.b16 {%0,%1,%2,%3}, [%4];"
                 : "=r"(r0), "=r"(r1), "=r"(r2), "=r"(r3) : "r"(a));
}
__device__ __forceinline__ void mma_bf16(float* c, const uint32_t* a, const uint32_t* b) {
    asm volatile("mma.sync.aligned.m16n8k16.row.col.f32.bf16.bf16.f32 "
                 "{%0,%1,%2,%3}, {%4,%5,%6,%7}, {%8,%9}, {%0,%1,%2,%3};"
                 : "+f"(c[0]), "+f"(c[1]), "+f"(c[2]), "+f"(c[3])
                 : "r"(a[0]), "r"(a[1]), "r"(a[2]), "r"(a[3]),
                   "r"(b[0]), "r"(b[1]));
}
__device__ __forceinline__ void split_bf(float2 v, uint32_t& hi, uint32_t& lo) {
    __nv_bfloat16 h0 = __float2bfloat16(v.x);
    __nv_bfloat16 h1 = __float2bfloat16(v.y);
    __nv_bfloat162 hp = __halves2bfloat162(h0, h1);
    __nv_bfloat162 lp = __halves2bfloat162(
        __float2bfloat16(v.x - __bfloat162float(h0)),
        __float2bfloat16(v.y - __bfloat162float(h1)));
    hi = *(uint32_t*)&hp;
    lo = *(uint32_t*)&lp;
}
__device__ __forceinline__ void red_add_v4(float* addr, float4 v) {
    asm volatile("red.global.add.v4.f32 [%0], {%1, %2, %3, %4};"
                 :: "l"(addr), "f"(v.x), "f"(v.y), "f"(v.z), "f"(v.w)
                 : "memory");
}

// smem layout (byte offsets in dynamic smem)
#define B_HI   0             // 128 rows * 272 B
#define B_LO   34816
#define SM_BIAS 69632        // 128 f32
#define SMEMSZ 70144

// ---------------- kernel 0: detect edge_index dtype ----------------
__global__ void probe_kernel(const int* __restrict__ e) {
    __shared__ int nz;
    if (threadIdx.x == 0) nz = 0;
    __syncthreads();
    int v = e[threadIdx.x * 2 + 1];
    if (v != 0) atomicAdd(&nz, 1);
    __syncthreads();
    if (threadIdx.x == 0) g_idx_is64 = (nz == 0) ? 1 : 0;
}

// ---------------- kernel 1: zero aggr + stats ----------------
__global__ void zero_kernel() {
    int idx = blockIdx.x * blockDim.x + threadIdx.x;
    const int n4 = (N_NODES * D) / 4;
    if (idx < n4) ((float4*)g_aggr)[idx] = make_float4(0.f, 0.f, 0.f, 0.f);
    if (blockIdx.x == 0 && threadIdx.x < D) {
        g_sum[threadIdx.x] = 0.f;
        g_sumsq[threadIdx.x] = 0.f;
    }
}

// ---------------- kernel 2: convert weights to bf16 hi/lo (once) ----------
__global__ void wconv_kernel(const float* __restrict__ W_root,
                             const float* __restrict__ W_rel) {
    int idx = blockIdx.x * blockDim.x + threadIdx.x;   // 8192 threads
#pragma unroll
    for (int p = idx; p < 16384; p += 8192) {
        int k = p >> 6;
        int n2 = (p & 63) * 2;
        const float* W = (k < 128) ? (W_root + k * 128 + n2)
                                   : (W_rel + (k - 128) * 128 + n2);
        float2 v = *(const float2*)W;
        uint32_t hi, lo;
        split_bf(v, hi, lo);
        *(uint32_t*)((char*)gW_hi + (size_t)(k * 128 + n2) * 2) = hi;
        *(uint32_t*)((char*)gW_lo + (size_t)(k * 128 + n2) * 2) = lo;
    }
}

// ---------------- shared GEMM body ----------------
// 256 threads = 8 warps; warp w handles rows m0+w*16 .. +16, all 128 cols.
// A: fp32 loaded direct from global into mma fragment layout, hi/lo split in regs.
// B: bf16 hi/lo resident in smem for all K=128 (one fill, one sync).
template<int PHASE>   // 0: h = x@W_root (raw); 1: h += aggr@W_rel + bias
__device__ __forceinline__ void gemm_body(const float* __restrict__ A,
                                          const float* __restrict__ bias,
                                          char* smem, uint32_t sb, int blk) {
    const int tid = threadIdx.x;
    const int w = tid >> 5;
    const int lid = tid & 31;
    const int m0 = blk * 128;

    // fill B smem: 2048 16B chunks each for hi and lo
#pragma unroll
    for (int i = 0; i < 8; i++) {
        int ch = tid + i * 256;
        int row = ch >> 4, c16 = ch & 15;
        size_t gsrc = (size_t)((PHASE * 128 + row) * 128 + c16 * 8) * 2;
        *(uint4*)(smem + B_HI + row * 272 + c16 * 16) = *(const uint4*)((const char*)gW_hi + gsrc);
        *(uint4*)(smem + B_LO + row * 272 + c16 * 16) = *(const uint4*)((const char*)gW_lo + gsrc);
    }
    if (PHASE == 1 && tid < 128) ((float*)(smem + SM_BIAS))[tid] = bias[tid];
    __syncthreads();

    float acc[16][4];
#pragma unroll
    for (int q = 0; q < 16; q++)
#pragma unroll
        for (int c = 0; c < 4; c++) acc[q][c] = 0.f;

    const int r = lid >> 2;
    const int cq = (lid & 3) * 2;
    const int m = m0 + w * 16 + r;
    const bool v0 = m < N_NODES;
    const bool v1 = (m + 8) < N_NODES;
    const float* pr0 = A + (size_t)m * D + cq;
    const float* pr1 = A + (size_t)(m + 8) * D + cq;
    const float2 fz = make_float2(0.f, 0.f);

#pragma unroll
    for (int s = 0; s < 8; s++) {          // K = 128, 8 k16 steps
        const int ko = s * 16;
        float2 x00 = v0 ? *(const float2*)(pr0 + ko) : fz;
        float2 x10 = v1 ? *(const float2*)(pr1 + ko) : fz;
        float2 x01 = v0 ? *(const float2*)(pr0 + ko + 8) : fz;
        float2 x11 = v1 ? *(const float2*)(pr1 + ko + 8) : fz;
        uint32_t ah[4], al[4];
        split_bf(x00, ah[0], al[0]);
        split_bf(x10, ah[1], al[1]);
        split_bf(x01, ah[2], al[2]);
        split_bf(x11, ah[3], al[3]);

        const uint32_t rowa = sb + (uint32_t)((s * 16 + (lid & 15)) * 272 + (lid >> 4) * 16);
#pragma unroll
        for (int q8 = 0; q8 < 8; q8++) {   // 16-col blocks
            uint32_t bh[4], bl[4];
            uint32_t ba = rowa + (uint32_t)(q8 * 32);
            ldsm_x4_t(bh[0], bh[1], bh[2], bh[3], ba + B_HI);
            ldsm_x4_t(bl[0], bl[1], bl[2], bl[3], ba + B_LO);
            float* c0 = acc[q8 * 2];
            float* c1 = acc[q8 * 2 + 1];
            mma_bf16(c0, ah, bh);
            mma_bf16(c0, ah, bl);
            mma_bf16(c0, al, bh);
            mma_bf16(c1, ah, bh + 2);
            mma_bf16(c1, ah, bl + 2);
            mma_bf16(c1, al, bh + 2);
        }
    }

    // epilogue
    const int n0 = cq;
    if (PHASE == 0) {
#pragma unroll
        for (int q = 0; q < 16; q++) {
            int n = q * 8 + n0;
            if (v0) *(float2*)(g_h + (size_t)m * D + n) = make_float2(acc[q][0], acc[q][1]);
            if (v1) *(float2*)(g_h + (size_t)(m + 8) * D + n) = make_float2(acc[q][2], acc[q][3]);
        }
    } else {
        const float* bs = (const float*)(smem + SM_BIAS);
#pragma unroll
        for (int q = 0; q < 16; q++) {
            int n = q * 8 + n0;
            float b0 = bs[n], b1 = bs[n + 1];
            if (v0) {
                float2 o = *(const float2*)(g_h + (size_t)m * D + n);
                o.x += acc[q][0] + b0;
                o.y += acc[q][1] + b1;
                *(float2*)(g_h + (size_t)m * D + n) = o;
            }
            if (v1) {
                float2 o = *(const float2*)(g_h + (size_t)(m + 8) * D + n);
                o.x += acc[q][2] + b0;
                o.y += acc[q][3] + b1;
                *(float2*)(g_h + (size_t)(m + 8) * D + n) = o;
            }
        }
    }
}

// ---------------- scatter body (block handles batches of 4 edges/warp) ----
__device__ __forceinline__ void scatter_body(const void* __restrict__ edge_index,
                                             const float* __restrict__ x, int blk) {
    const int wid = threadIdx.x >> 5;
    const int lane = threadIdx.x & 31;
    const int wglob = blk * 8 + wid;          // 0..6255
    const int WSTRIDE = 6256;
    const bool is64 = (g_idx_is64 != 0);

#pragma unroll 1
    for (int it = 0; it < 64; it++) {
        int e0 = (wglob + it * WSTRIDE) * 4;
        if (e0 >= N_EDGES) break;
        long long s[4], d[4];
        if (is64) {
            const longlong2* e = (const longlong2*)edge_index;
            longlong2 p0 = e[(e0 >> 1)], p1 = e[(e0 >> 1) + 1];
            longlong2 q0 = e[(N_EDGES + e0) >> 1], q1 = e[((N_EDGES + e0) >> 1) + 1];
            s[0] = p0.x; s[1] = p0.y; s[2] = p1.x; s[3] = p1.y;
            d[0] = q0.x; d[1] = q0.y; d[2] = q1.x; d[3] = q1.y;
        } else {
            const int* e = (const int*)edge_index;
            int4 sv = *(const int4*)(e + e0);
            int4 dv = *(const int4*)(e + N_EDGES + e0);
            s[0] = sv.x; s[1] = sv.y; s[2] = sv.z; s[3] = sv.w;
            d[0] = dv.x; d[1] = dv.y; d[2] = dv.z; d[3] = dv.w;
        }
        int cnt = N_EDGES - e0; if (cnt > 4) cnt = 4;
        float4 v[4];
#pragma unroll
        for (int j = 0; j < 4; j++) {
            bool ok = (j < cnt) && ((unsigned long long)s[j] < N_NODES);
            v[j] = ok ? ((const float4*)(x + (size_t)s[j] * D))[lane]
                      : make_float4(0.f, 0.f, 0.f, 0.f);
        }
#pragma unroll
        for (int j = 0; j < 4; j++) {
            if ((j < cnt) && ((unsigned long long)s[j] < N_NODES)
                          && ((unsigned long long)d[j] < N_NODES))
                red_add_v4(g_aggr + (size_t)d[j] * D + lane * 4, v[j]);
        }
    }
}

// ---------------- phase A: heterogeneous scatter || x@W_root ----------------
__global__ void __launch_bounds__(256, 2)
hetA_kernel(const float* __restrict__ x, const void* __restrict__ eidx) {
    extern __shared__ char smem[];
    int id = blockIdx.x >> 1;
    if (blockIdx.x & 1) {
        scatter_body(eidx, x, id);
    } else {
        gemm_body<0>(x, nullptr, smem, smem_u32(smem), id);
    }
}

// ---------------- phase B: aggr@W_rel + bias, accumulate into g_h ----------
__global__ void __launch_bounds__(256, 2)
gemmB_kernel(const float* __restrict__ b_rel) {
    extern __shared__ char smem[];
    gemm_body<1>(g_aggr, b_rel, smem, smem_u32(smem), blockIdx.x);
}

// ---------------- stats: column sum / sumsq of g_h ----------------
__global__ void stats_kernel() {
    __shared__ float ssum[D], ssq[D];
    int tid = threadIdx.x;
    if (tid < D) { ssum[tid] = 0.f; ssq[tid] = 0.f; }
    __syncthreads();
    const int n4 = (N_NODES * D) / 4;
    int c4 = (tid & 31) * 4;
    float s0 = 0.f, s1 = 0.f, s2 = 0.f, s3 = 0.f;
    float q0 = 0.f, q1 = 0.f, q2 = 0.f, q3 = 0.f;
    for (int idx = blockIdx.x * 256 + tid; idx < n4; idx += gridDim.x * 256) {
        float4 h = ((const float4*)g_h)[idx];
        s0 += h.x; s1 += h.y; s2 += h.z; s3 += h.w;
        q0 += h.x * h.x; q1 += h.y * h.y; q2 += h.z * h.z; q3 += h.w * h.w;
    }
    atomicAdd(&ssum[c4 + 0], s0); atomicAdd(&ssum[c4 + 1], s1);
    atomicAdd(&ssum[c4 + 2], s2); atomicAdd(&ssum[c4 + 3], s3);
    atomicAdd(&ssq[c4 + 0], q0);  atomicAdd(&ssq[c4 + 1], q1);
    atomicAdd(&ssq[c4 + 2], q2);  atomicAdd(&ssq[c4 + 3], q3);
    __syncthreads();
    if (tid < D) {
        atomicAdd(&g_sum[tid], ssum[tid]);
        atomicAdd(&g_sumsq[tid], ssq[tid]);
    }
}

// ---------------- fused finalize + normalize + ReLU ----------------
__global__ void norm_kernel(const float* __restrict__ gamma,
                            const float* __restrict__ beta,
                            float* __restrict__ out) {
    __shared__ float ssc[D], ssh[D];
    int t = threadIdx.x;
    if (t < D) {
        float inv_n = 1.0f / (float)N_NODES;
        float mean = g_sum[t] * inv_n;
        float var = g_sumsq[t] * inv_n - mean * mean;
        float sc = gamma[t] * rsqrtf(var + EPS);
        ssc[t] = sc;
        ssh[t] = beta[t] - mean * sc;
    }
    __syncthreads();
    int idx = blockIdx.x * blockDim.x + t;
    const int n4 = (N_NODES * D) / 4;
    if (idx >= n4) return;
    int c4 = (idx & (D / 4 - 1)) * 4;
    float4 h = ((const float4*)g_h)[idx];
    float4 o;
    o.x = fmaxf(h.x * ssc[c4 + 0] + ssh[c4 + 0], 0.f);
    o.y = fmaxf(h.y * ssc[c4 + 1] + ssh[c4 + 1], 0.f);
    o.z = fmaxf(h.z * ssc[c4 + 2] + ssh[c4 + 2], 0.f);
    o.w = fmaxf(h.w * ssc[c4 + 3] + ssh[c4 + 3], 0.f);
    ((float4*)out)[idx] = o;
}

// ---------------- launch ----------------
extern "C" void kernel_launch(void* const* d_in, const int* in_sizes, int n_in,
                              void* d_out, int out_size) {
    const float* x      = (const float*)d_in[0];
    const void*  eidx   = d_in[1];
    const float* W_root = (const float*)d_in[2];
    const float* W_rel  = (const float*)d_in[3];
    const float* b_rel  = (const float*)d_in[4];
    const float* gamma  = (const float*)d_in[5];
    const float* beta   = (const float*)d_in[6];
    float*       out    = (float*)d_out;

    cudaFuncSetAttribute(hetA_kernel,
                         cudaFuncAttributeMaxDynamicSharedMemorySize, SMEMSZ);
    cudaFuncSetAttribute(gemmB_kernel,
                         cudaFuncAttributeMaxDynamicSharedMemorySize, SMEMSZ);

    probe_kernel<<<1, 64>>>((const int*)eidx);

    const int n4 = (N_NODES * D) / 4;
    zero_kernel<<<(n4 + 255) / 256, 256>>>();

    wconv_kernel<<<32, 256>>>(W_root, W_rel);

    hetA_kernel<<<1564, 256, SMEMSZ>>>(x, eidx);

    gemmB_kernel<<<782, 256, SMEMSZ>>>(b_rel);

    stats_kernel<<<128, 256>>>();

    norm_kernel<<<(n4 + 255) / 256, 256>>>(gamma, beta, out);
}